// round 9
// baseline (speedup 1.0000x reference)
#include <cuda_runtime.h>
#include <math.h>
#include <stdint.h>

#define kN 50000
#define kE 600000
#define kH 128
#define kG 500
#define kC 10
#define NUM_GIN 3
#define NSTAT 256   // partial-stat blocks for big tensors

// ---------------- device scratch (static; no allocation) ----------------
__device__ __align__(16) float g_bufA[kN * kH];
__device__ __align__(16) float g_bufB[kN * kH];
__device__ __align__(16) float g_bufC[kN * kH];
__device__ int   g_cnt[kN];
__device__ int   g_rowptr[kN + 1];
__device__ int   g_cursor[kN];
__device__ int   g_srcsorted[kE];
__device__ __align__(16) float g_psum[NSTAT * kH];
__device__ __align__(16) float g_psq[NSTAT * kH];
__device__ __align__(16) float g_colsum[kH];
__device__ __align__(16) float g_colsq[kH];
__device__ __align__(16) float g_mean[kH];
__device__ __align__(16) float g_rstd[kH];
__device__ __align__(16) float g_Wt[kH * kH];
__device__ __align__(16) float g_bt[kH];
__device__ __align__(16) float g_Bpack[7][16384];  // packed tf32 B fragments
__device__ __align__(16) float g_pool[kG * kH];
__device__ __align__(16) float g_pool2[kG * kH];

__device__ __forceinline__ uint32_t f2tf32(float f) {
    uint32_t r;
    asm("cvt.rna.tf32.f32 %0, %1;" : "=r"(r) : "f"(f));
    return r;
}

// ---------------- CSR build ----------------
__global__ void zero_cnt_kernel() {
    int i = blockIdx.x * blockDim.x + threadIdx.x;
    if (i < kN) g_cnt[i] = 0;
}

__global__ void edge_count_kernel(const int* __restrict__ ei) {
    int e = blockIdx.x * blockDim.x + threadIdx.x;
    if (e < kE) atomicAdd(&g_cnt[ei[kE + e]], 1);
}

__global__ void scan_kernel() {
    __shared__ int s[1024];
    int t = threadIdx.x;
    const int CH = (kN + 1023) / 1024;
    int base = t * CH;
    int sum = 0;
    for (int i = 0; i < CH; i++) {
        int idx = base + i;
        if (idx < kN) sum += g_cnt[idx];
    }
    s[t] = sum;
    __syncthreads();
    for (int off = 1; off < 1024; off <<= 1) {
        int v = (t >= off) ? s[t - off] : 0;
        __syncthreads();
        s[t] += v;
        __syncthreads();
    }
    int run = (t == 0) ? 0 : s[t - 1];
    for (int i = 0; i < CH; i++) {
        int idx = base + i;
        if (idx < kN) {
            g_rowptr[idx] = run;
            g_cursor[idx] = run;
            run += g_cnt[idx];
        }
    }
    if (t == 1023) g_rowptr[kN] = kE;
}

__global__ void edge_scatter_kernel(const int* __restrict__ ei) {
    int e = blockIdx.x * blockDim.x + threadIdx.x;
    if (e < kE) {
        int d = ei[kE + e];
        int p = atomicAdd(&g_cursor[d], 1);
        g_srcsorted[p] = ei[e];
    }
}

// ---------------- column stats: per-block partials ----------------
__global__ void colstats_part_kernel(const float* __restrict__ in, int rows) {
    int col = threadIdx.x & 127;
    int half = threadIdx.x >> 7;
    float s = 0.f, q = 0.f;
    for (int r = blockIdx.x * 2 + half; r < rows; r += gridDim.x * 2) {
        float v = in[r * kH + col];
        s += v;
        q += v * v;
    }
    __shared__ float ss[256], qq[256];
    ss[threadIdx.x] = s;
    qq[threadIdx.x] = q;
    __syncthreads();
    if (threadIdx.x < 128) {
        g_psum[blockIdx.x * kH + col] = ss[threadIdx.x] + ss[threadIdx.x + 128];
        g_psq[blockIdx.x * kH + col] = qq[threadIdx.x] + qq[threadIdx.x + 128];
    }
}

__global__ void finalize_fold_kernel(int nb, float inv_n, int do_fold,
                                     const float* __restrict__ W, const float* __restrict__ b,
                                     const float* __restrict__ gamma, const float* __restrict__ beta) {
    __shared__ float sm_sg[kH], sm_off[kH];
    int j = threadIdx.x;
    float s = 0.f, q = 0.f;
    for (int bi = 0; bi < nb; bi++) {
        s += g_psum[bi * kH + j];
        q += g_psq[bi * kH + j];
    }
    float m = s * inv_n;
    float v = q * inv_n - m * m;
    float rs = rsqrtf(fmaxf(v, 0.f) + 1e-5f);
    g_mean[j] = m;
    g_rstd[j] = rs;
    if (!do_fold) return;
    float gm = gamma[j], bt = beta[j];
    sm_sg[j] = rs * gm;
    sm_off[j] = bt - m * rs * gm;
    __syncthreads();
    float acc = b[j];
    for (int k = 0; k < kH; k++) {
        float w = W[k * kH + j];
        g_Wt[k * kH + j] = w * sm_sg[k];
        acc += sm_off[k] * w;
    }
    g_bt[j] = acc;
}

__global__ void zero_stats_kernel() {
    int t = threadIdx.x;
    if (t < kH) { g_colsum[t] = 0.f; g_colsq[t] = 0.f; }
}
__global__ void finalize_kernel(float inv_n) {
    int j = threadIdx.x;
    float m = g_colsum[j] * inv_n;
    float v = g_colsq[j] * inv_n - m * m;
    g_mean[j] = m;
    g_rstd[j] = rsqrtf(fmaxf(v, 0.f) + 1e-5f);
}

// ---------------- B-fragment pre-pack ----------------
__global__ void pack_bfrag_kernel(const float* __restrict__ W, float* __restrict__ dst) {
    int i = blockIdx.x * 256 + threadIdx.x;
    if (i >= 4096) return;
    int lane = i & 31;
    int kk2 = (i >> 5) & 7;
    int nt = i >> 8;
    int g = lane >> 2, tq = lane & 3;
    int n = nt * 8 + g;
    int k0 = kk2 * 16 + tq;
    float4 v;
    v.x = __uint_as_float(f2tf32(W[(k0)      * kH + n]));
    v.y = __uint_as_float(f2tf32(W[(k0 + 4)  * kH + n]));
    v.z = __uint_as_float(f2tf32(W[(k0 + 8)  * kH + n]));
    v.w = __uint_as_float(f2tf32(W[(k0 + 12) * kH + n]));
    ((float4*)dst)[i] = v;
}

// ---------------- tf32 mma.sync GEMM v5: B direct from L1, 4 CTAs/SM ----------------
#define PAD 132   // A-frag LDS bank = 4g+tq -> conflict-free
#define TF_SMEM ((64 * PAD + 128) * 4)

__global__ __launch_bounds__(128, 4) void gemm_tf32_kernel(
    const float* __restrict__ A, const float* __restrict__ Bpack,
    const float* __restrict__ bias, float* __restrict__ out,
    int rows, int mode_in, int relu_out,
    const float* __restrict__ gamma, const float* __restrict__ beta) {
    extern __shared__ float sm[];
    float* As = sm;                    // [64][PAD]
    float* bias_s = sm + 64 * PAD;     // [128]

    int t = threadIdx.x;
    int wid = t >> 5, lane = t & 31;
    int row0 = blockIdx.x * 64;

    if (t < 128) bias_s[t] = bias[t];

    // stage A tile (64x128) with optional BN+relu, tf32-rounded
#pragma unroll
    for (int i = 0; i < 16; i++) {
        int idx4 = i * 128 + t;
        int r = idx4 >> 5;
        int c4 = idx4 & 31;
        int grow = row0 + r;
        float4 v = make_float4(0.f, 0.f, 0.f, 0.f);
        if (grow < rows) v = *(const float4*)(A + (size_t)grow * kH + c4 * 4);
        if (mode_in) {
            int k = c4 * 4;
            v.x = fmaxf(fmaf(v.x - g_mean[k + 0], g_rstd[k + 0] * gamma[k + 0], beta[k + 0]), 0.f);
            v.y = fmaxf(fmaf(v.y - g_mean[k + 1], g_rstd[k + 1] * gamma[k + 1], beta[k + 1]), 0.f);
            v.z = fmaxf(fmaf(v.z - g_mean[k + 2], g_rstd[k + 2] * gamma[k + 2], beta[k + 2]), 0.f);
            v.w = fmaxf(fmaf(v.w - g_mean[k + 3], g_rstd[k + 3] * gamma[k + 3], beta[k + 3]), 0.f);
        }
        float* dst = As + r * PAD + c4 * 4;
        dst[0] = __uint_as_float(f2tf32(v.x));
        dst[1] = __uint_as_float(f2tf32(v.y));
        dst[2] = __uint_as_float(f2tf32(v.z));
        dst[3] = __uint_as_float(f2tf32(v.w));
    }
    __syncthreads();

    int g = lane >> 2;
    int tq = lane & 3;
    int wrow = wid * 16;

    float acc[16][4];
#pragma unroll
    for (int nt = 0; nt < 16; nt++)
#pragma unroll
        for (int j = 0; j < 4; j++) acc[nt][j] = 0.f;

    const float* abase = As + (wrow + g) * PAD + tq;
    const float4* bp = ((const float4*)Bpack) + lane;   // L1-resident (64 KB total)

#pragma unroll
    for (int kk2 = 0; kk2 < 8; kk2++) {
        const float* ap = abase + kk2 * 16;
        uint32_t a0[4], a1[4];
        a0[0] = __float_as_uint(ap[0]);
        a0[1] = __float_as_uint(ap[8 * PAD]);
        a0[2] = __float_as_uint(ap[4]);
        a0[3] = __float_as_uint(ap[8 * PAD + 4]);
        a1[0] = __float_as_uint(ap[8]);
        a1[1] = __float_as_uint(ap[8 * PAD + 8]);
        a1[2] = __float_as_uint(ap[12]);
        a1[3] = __float_as_uint(ap[8 * PAD + 12]);
        const float4* bk = bp + kk2 * 32;
#pragma unroll
        for (int nt = 0; nt < 16; nt++) {
            float4 b = __ldg(&bk[nt * 256]);
            asm volatile(
                "mma.sync.aligned.m16n8k8.row.col.f32.tf32.tf32.f32 "
                "{%0,%1,%2,%3}, {%4,%5,%6,%7}, {%8,%9}, {%0,%1,%2,%3};"
                : "+f"(acc[nt][0]), "+f"(acc[nt][1]), "+f"(acc[nt][2]), "+f"(acc[nt][3])
                : "r"(a0[0]), "r"(a0[1]), "r"(a0[2]), "r"(a0[3]),
                  "r"(__float_as_uint(b.x)), "r"(__float_as_uint(b.y)));
            asm volatile(
                "mma.sync.aligned.m16n8k8.row.col.f32.tf32.tf32.f32 "
                "{%0,%1,%2,%3}, {%4,%5,%6,%7}, {%8,%9}, {%0,%1,%2,%3};"
                : "+f"(acc[nt][0]), "+f"(acc[nt][1]), "+f"(acc[nt][2]), "+f"(acc[nt][3])
                : "r"(a1[0]), "r"(a1[1]), "r"(a1[2]), "r"(a1[3]),
                  "r"(__float_as_uint(b.z)), "r"(__float_as_uint(b.w)));
        }
    }

    int r0 = row0 + wrow + g;
    int r1 = r0 + 8;
#pragma unroll
    for (int nt = 0; nt < 16; nt++) {
        int col = nt * 8 + tq * 2;
        float bx = bias_s[col], by = bias_s[col + 1];
        float o0 = acc[nt][0] + bx, o1 = acc[nt][1] + by;
        float o2 = acc[nt][2] + bx, o3 = acc[nt][3] + by;
        if (relu_out) {
            o0 = fmaxf(o0, 0.f); o1 = fmaxf(o1, 0.f);
            o2 = fmaxf(o2, 0.f); o3 = fmaxf(o3, 0.f);
        }
        if (r0 < rows) *(float2*)(out + (size_t)r0 * kH + col) = make_float2(o0, o1);
        if (r1 < rows) *(float2*)(out + (size_t)r1 * kH + col) = make_float2(o2, o3);
    }
}

// ---------------- scalar GEMM (small, rows<=500) with fused stats ----------------
#define GEMM_SMEM ((128 * 128 + 64 * 128 + 256) * 4)

__global__ __launch_bounds__(256, 2) void gemm_kernel(
    const float* __restrict__ A, const float* __restrict__ W,
    const float* __restrict__ bias, float* __restrict__ out,
    int rows, int mode_in, int relu_out, int do_stats,
    const float* __restrict__ gamma, const float* __restrict__ beta) {
    extern __shared__ float smf[];
    float* Ws = smf;
    float* As = smf + 128 * 128;
    float* colS = As + 64 * 128;
    float* colQ = colS + 128;

    int t = threadIdx.x;
    if (t < 128) { colS[t] = 0.f; colQ[t] = 0.f; }
    int row0 = blockIdx.x * 64;

    const float4* W4 = (const float4*)W;
    float4* Ws4 = (float4*)Ws;
#pragma unroll
    for (int i = 0; i < 16; i++) Ws4[i * 256 + t] = W4[i * 256 + t];

#pragma unroll
    for (int i = 0; i < 8; i++) {
        int idx4 = i * 256 + t;
        int r = idx4 >> 5;
        int c4 = idx4 & 31;
        int grow = row0 + r;
        float4 v = make_float4(0.f, 0.f, 0.f, 0.f);
        if (grow < rows) v = *(const float4*)(A + (size_t)grow * kH + c4 * 4);
        if (mode_in) {
            int k = c4 * 4;
            v.x = fmaxf(fmaf(v.x - g_mean[k + 0], g_rstd[k + 0] * gamma[k + 0], beta[k + 0]), 0.f);
            v.y = fmaxf(fmaf(v.y - g_mean[k + 1], g_rstd[k + 1] * gamma[k + 1], beta[k + 1]), 0.f);
            v.z = fmaxf(fmaf(v.z - g_mean[k + 2], g_rstd[k + 2] * gamma[k + 2], beta[k + 2]), 0.f);
            v.w = fmaxf(fmaf(v.w - g_mean[k + 3], g_rstd[k + 3] * gamma[k + 3], beta[k + 3]), 0.f);
        }
        *(float4*)(As + r * kH + c4 * 4) = v;
    }
    __syncthreads();

    int tc = (t & 31) * 4;
    int tr = (t >> 5) * 8;
    float acc[8][4];
#pragma unroll
    for (int i = 0; i < 8; i++)
#pragma unroll
        for (int j = 0; j < 4; j++) acc[i][j] = 0.f;

#pragma unroll 8
    for (int k = 0; k < kH; k++) {
        float4 w = *(const float4*)(Ws + k * kH + tc);
#pragma unroll
        for (int i = 0; i < 8; i++) {
            float a = As[(tr + i) * kH + k];
            acc[i][0] = fmaf(a, w.x, acc[i][0]);
            acc[i][1] = fmaf(a, w.y, acc[i][1]);
            acc[i][2] = fmaf(a, w.z, acc[i][2]);
            acc[i][3] = fmaf(a, w.w, acc[i][3]);
        }
    }

    float4 b4 = *(const float4*)(bias + tc);
    float sl[4] = {0.f, 0.f, 0.f, 0.f}, ql[4] = {0.f, 0.f, 0.f, 0.f};
#pragma unroll
    for (int i = 0; i < 8; i++) {
        int grow = row0 + tr + i;
        float o0 = acc[i][0] + b4.x;
        float o1 = acc[i][1] + b4.y;
        float o2 = acc[i][2] + b4.z;
        float o3 = acc[i][3] + b4.w;
        if (relu_out) {
            o0 = fmaxf(o0, 0.f); o1 = fmaxf(o1, 0.f);
            o2 = fmaxf(o2, 0.f); o3 = fmaxf(o3, 0.f);
        }
        if (grow < rows) {
            *(float4*)(out + (size_t)grow * kH + tc) = make_float4(o0, o1, o2, o3);
            if (do_stats) {
                sl[0] += o0; ql[0] += o0 * o0;
                sl[1] += o1; ql[1] += o1 * o1;
                sl[2] += o2; ql[2] += o2 * o2;
                sl[3] += o3; ql[3] += o3 * o3;
            }
        }
    }
    if (do_stats) {
        atomicAdd(&colS[tc + 0], sl[0]); atomicAdd(&colQ[tc + 0], ql[0]);
        atomicAdd(&colS[tc + 1], sl[1]); atomicAdd(&colQ[tc + 1], ql[1]);
        atomicAdd(&colS[tc + 2], sl[2]); atomicAdd(&colQ[tc + 2], ql[2]);
        atomicAdd(&colS[tc + 3], sl[3]); atomicAdd(&colQ[tc + 3], ql[3]);
        __syncthreads();
        if (t < 128) {
            atomicAdd(&g_colsum[t], colS[t]);
            atomicAdd(&g_colsq[t], colQ[t]);
        }
    }
}

// ---------------- GIN aggregation (unroll 4) ----------------
__global__ void agg_kernel(const float* __restrict__ h, float* __restrict__ z) {
    int gidx = blockIdx.x * blockDim.x + threadIdx.x;
    int node = gidx >> 5;
    int lane = gidx & 31;
    if (node >= kN) return;
    int beg = g_rowptr[node], end = g_rowptr[node + 1];
    const float4* h4 = (const float4*)h;
    float4 acc = h4[node * 32 + lane];
    float4 acc2 = make_float4(0.f, 0.f, 0.f, 0.f);
    int e = beg;
    for (; e + 4 <= end; e += 4) {
        int s0 = g_srcsorted[e], s1 = g_srcsorted[e + 1];
        int s2 = g_srcsorted[e + 2], s3 = g_srcsorted[e + 3];
        float4 v0 = h4[s0 * 32 + lane];
        float4 v1 = h4[s1 * 32 + lane];
        float4 v2 = h4[s2 * 32 + lane];
        float4 v3 = h4[s3 * 32 + lane];
        acc.x += v0.x + v1.x; acc.y += v0.y + v1.y;
        acc.z += v0.z + v1.z; acc.w += v0.w + v1.w;
        acc2.x += v2.x + v3.x; acc2.y += v2.y + v3.y;
        acc2.z += v2.z + v3.z; acc2.w += v2.w + v3.w;
    }
    for (; e < end; e++) {
        int s = g_srcsorted[e];
        float4 v = h4[s * 32 + lane];
        acc.x += v.x; acc.y += v.y; acc.z += v.z; acc.w += v.w;
    }
    acc.x += acc2.x; acc.y += acc2.y; acc.z += acc2.z; acc.w += acc2.w;
    ((float4*)z)[node * 32 + lane] = acc;
}

// ---------------- pooling: block per graph (batch sorted) ----------------
__global__ void pool_seg_kernel(const float* __restrict__ h, const int* __restrict__ batch) {
    int g = blockIdx.x;
    int t = threadIdx.x;
    int lo = 0, hi = kN;
    while (lo < hi) { int m = (lo + hi) >> 1; if (batch[m] < g) lo = m + 1; else hi = m; }
    int s = lo;
    lo = s; hi = kN;
    while (lo < hi) { int m = (lo + hi) >> 1; if (batch[m] < g + 1) lo = m + 1; else hi = m; }
    int e = lo;
    float acc = 0.f;
    for (int n = s; n < e; n++) acc += h[(size_t)n * kH + t];
    g_pool[g * kH + t] = acc;
}

// ---------------- final head ----------------
__global__ void final_kernel(const float* __restrict__ g2,
                             const float* __restrict__ gamma_h, const float* __restrict__ beta_h,
                             const float* __restrict__ Wcls, const float* __restrict__ bcls,
                             float* __restrict__ out) {
    int row = blockIdx.x;
    int t = threadIdx.x;
    __shared__ float y[kH];
    __shared__ float logits[kC];
    float v = g2[row * kH + t];
    v = fmaf(v - g_mean[t], g_rstd[t] * gamma_h[t], beta_h[t]);
    y[t] = v;
    __syncthreads();
    if (t < kC) {
        float acc = bcls[t];
        for (int k = 0; k < kH; k++) acc = fmaf(y[k], Wcls[k * kC + t], acc);
        logits[t] = acc;
    }
    __syncthreads();
    if (t == 0) {
        float mx = -1e30f;
        for (int c = 0; c < kC; c++) mx = fmaxf(mx, logits[c]);
        float se = 0.f;
        for (int c = 0; c < kC; c++) se += expf(logits[c] - mx);
        float lse = logf(se) + mx;
        for (int c = 0; c < kC; c++) out[row * kC + c] = logits[c] - lse;
    }
}

// ---------------- launcher ----------------
extern "C" void kernel_launch(void* const* d_in, const int* in_sizes, int n_in,
                              void* d_out, int out_size) {
    int iX = 0, iEI = 1, iB = 2, iGF = 3, iBF = 4, iWF = 5, ibF = 6,
        iW1 = 7, ib1 = 8, iGG = 9, iGB = 10, iW2 = 11, ib2 = 12,
        iGFC = 13, iBFC = 14, iWFC = 15, ibFC = 16, iGH = 17, iBH = 18,
        iWC = 19, ibC = 20;
    if (n_in >= 21 && in_sizes[1] != 2 * kE) {
        iGF = 1; iBF = 2; iWF = 3; ibF = 4; iW1 = 5; ib1 = 6; iGG = 7; iGB = 8;
        iW2 = 9; ib2 = 10; iGFC = 11; iBFC = 12; iWFC = 13; ibFC = 14;
        iGH = 15; iBH = 16; iWC = 17; ibC = 18; iEI = 19; iB = 20;
    }
    const float* x          = (const float*)d_in[iX];
    const int*   ei         = (const int*)d_in[iEI];
    const int*   batch      = (const int*)d_in[iB];
    const float* gamma_feat = (const float*)d_in[iGF];
    const float* beta_feat  = (const float*)d_in[iBF];
    const float* W_feat     = (const float*)d_in[iWF];
    const float* b_feat     = (const float*)d_in[ibF];
    const float* gin_W1     = (const float*)d_in[iW1];
    const float* gin_b1     = (const float*)d_in[ib1];
    const float* gin_gamma  = (const float*)d_in[iGG];
    const float* gin_beta   = (const float*)d_in[iGB];
    const float* gin_W2     = (const float*)d_in[iW2];
    const float* gin_b2     = (const float*)d_in[ib2];
    const float* gamma_fc   = (const float*)d_in[iGFC];
    const float* beta_fc    = (const float*)d_in[iBFC];
    const float* W_fc       = (const float*)d_in[iWFC];
    const float* b_fc       = (const float*)d_in[ibFC];
    const float* gamma_h    = (const float*)d_in[iGH];
    const float* beta_h     = (const float*)d_in[iBH];
    const float* W_cls      = (const float*)d_in[iWC];
    const float* b_cls      = (const float*)d_in[ibC];
    float* out = (float*)d_out;

    cudaFuncSetAttribute(gemm_kernel, cudaFuncAttributeMaxDynamicSharedMemorySize, GEMM_SMEM);
    cudaFuncSetAttribute(gemm_tf32_kernel, cudaFuncAttributeMaxDynamicSharedMemorySize, TF_SMEM);

    float *bufA, *bufB, *bufC, *pool, *pool2, *Wt, *bt, *Bpack;
    cudaGetSymbolAddress((void**)&bufA, g_bufA);
    cudaGetSymbolAddress((void**)&bufB, g_bufB);
    cudaGetSymbolAddress((void**)&bufC, g_bufC);
    cudaGetSymbolAddress((void**)&pool, g_pool);
    cudaGetSymbolAddress((void**)&pool2, g_pool2);
    cudaGetSymbolAddress((void**)&Wt, g_Wt);
    cudaGetSymbolAddress((void**)&bt, g_bt);
    cudaGetSymbolAddress((void**)&Bpack, g_Bpack);

    const int TB = 256;
    const int gridN = (kN + TB - 1) / TB;
    const int gridE = (kE + TB - 1) / TB;
    const int gridWarpN = (kN * 32 + TB - 1) / TB;
    const int gridTF = (kN + 63) / 64;
    const int gridGemmG = (kG + 63) / 64;

    // feat GEMM at profiled launch index 3.
    colstats_part_kernel<<<NSTAT, TB>>>(x, kN);                               // 0
    finalize_fold_kernel<<<1, 128>>>(NSTAT, 1.0f / kN, 1,
                                     W_feat, b_feat, gamma_feat, beta_feat);  // 1
    pack_bfrag_kernel<<<16, 256>>>(Wt, Bpack);                                // 2
    gemm_tf32_kernel<<<gridTF, 128, TF_SMEM>>>(x, Bpack, bt, bufA,
                                               kN, 0, 1, nullptr, nullptr);   // 3 <- profiled

    // CSR by dst (before first agg)
    zero_cnt_kernel<<<gridN, TB>>>();
    edge_count_kernel<<<gridE, TB>>>(ei);
    scan_kernel<<<1, 1024>>>();
    edge_scatter_kernel<<<gridE, TB>>>(ei);

    // pre-pack GIN weights
    for (int i = 0; i < NUM_GIN; i++) {
        pack_bfrag_kernel<<<16, 256>>>(gin_W1 + i * kH * kH, Bpack + (1 + i) * 16384);
        pack_bfrag_kernel<<<16, 256>>>(gin_W2 + i * kH * kH, Bpack + (4 + i) * 16384);
    }

    // GIN layers
    for (int i = 0; i < NUM_GIN; i++) {
        agg_kernel<<<gridWarpN, TB>>>(bufA, bufB);
        gemm_tf32_kernel<<<gridTF, 128, TF_SMEM>>>(bufB, Bpack + (1 + i) * 16384,
                                                   gin_b1 + i * kH, bufC, kN, 0, 0,
                                                   nullptr, nullptr);
        colstats_part_kernel<<<NSTAT, TB>>>(bufC, kN);
        finalize_fold_kernel<<<1, 128>>>(NSTAT, 1.0f / kN, 0,
                                         nullptr, nullptr, nullptr, nullptr);
        gemm_tf32_kernel<<<gridTF, 128, TF_SMEM>>>(bufC, Bpack + (4 + i) * 16384,
                                                   gin_b2 + i * kH, bufA, kN, 1, 1,
                                                   gin_gamma + i * kH, gin_beta + i * kH);
    }

    // pool (segment sum, batch sorted)
    pool_seg_kernel<<<kG, 128>>>(bufA, batch);

    // g2 = relu(BN(g) @ W_fc + b_fc) (BN folded); stats of g2 for bn_h
    colstats_part_kernel<<<4, TB>>>(pool, kG);
    finalize_fold_kernel<<<1, 128>>>(4, 1.0f / kG, 1, W_fc, b_fc, gamma_fc, beta_fc);
    zero_stats_kernel<<<1, 128>>>();
    gemm_kernel<<<gridGemmG, TB, GEMM_SMEM>>>(pool, Wt, bt, pool2, kG, 0, 1, 1, nullptr, nullptr);
    finalize_kernel<<<1, 128>>>(1.0f / kG);

    // classifier + log_softmax
    final_kernel<<<kG, 128>>>(pool2, gamma_h, beta_h, W_cls, b_cls, out);
}

// round 10
// speedup vs baseline: 1.0442x; 1.0442x over previous
#include <cuda_runtime.h>
#include <math.h>
#include <stdint.h>

#define kN 50000
#define kE 600000
#define kH 128
#define kG 500
#define kC 10
#define NUM_GIN 3
#define NSTAT 256   // partial-stat blocks for big tensors

// ---------------- device scratch (static; no allocation) ----------------
__device__ __align__(16) float g_bufA[kN * kH];
__device__ __align__(16) float g_bufB[kN * kH];
__device__ __align__(16) float g_bufC[kN * kH];
__device__ int   g_cnt[kN];
__device__ int   g_rowptr[kN + 1];
__device__ int   g_cursor[kN];
__device__ int   g_srcsorted[kE];
__device__ __align__(16) float g_psum[NSTAT * kH];
__device__ __align__(16) float g_psq[NSTAT * kH];
__device__ __align__(16) float g_colsum[kH];
__device__ __align__(16) float g_colsq[kH];
__device__ __align__(16) float g_mean[kH];
__device__ __align__(16) float g_rstd[kH];
__device__ __align__(16) float g_Wt[kH * kH];
__device__ __align__(16) float g_bt[kH];
__device__ __align__(16) uint4 g_Bpack[7][4096];   // packed bf16 hi/lo B fragments (64 KB each)
__device__ __align__(16) float g_pool[kG * kH];
__device__ __align__(16) float g_pool2[kG * kH];

// bf16 helpers
__device__ __forceinline__ uint32_t bfhi(float f) {
    uint16_t h;
    asm("cvt.rn.bf16.f32 %0, %1;" : "=h"(h) : "f"(f));
    return (uint32_t)h;
}
__device__ __forceinline__ float bf2f(uint32_t hbits) {
    return __uint_as_float(hbits << 16);
}

// ---------------- CSR build ----------------
__global__ void zero_cnt_kernel() {
    int i = blockIdx.x * blockDim.x + threadIdx.x;
    if (i < kN) g_cnt[i] = 0;
}

__global__ void edge_count_kernel(const int* __restrict__ ei) {
    int e = blockIdx.x * blockDim.x + threadIdx.x;
    if (e < kE) atomicAdd(&g_cnt[ei[kE + e]], 1);
}

__global__ void scan_kernel() {
    __shared__ int s[1024];
    int t = threadIdx.x;
    const int CH = (kN + 1023) / 1024;
    int base = t * CH;
    int sum = 0;
    for (int i = 0; i < CH; i++) {
        int idx = base + i;
        if (idx < kN) sum += g_cnt[idx];
    }
    s[t] = sum;
    __syncthreads();
    for (int off = 1; off < 1024; off <<= 1) {
        int v = (t >= off) ? s[t - off] : 0;
        __syncthreads();
        s[t] += v;
        __syncthreads();
    }
    int run = (t == 0) ? 0 : s[t - 1];
    for (int i = 0; i < CH; i++) {
        int idx = base + i;
        if (idx < kN) {
            g_rowptr[idx] = run;
            g_cursor[idx] = run;
            run += g_cnt[idx];
        }
    }
    if (t == 1023) g_rowptr[kN] = kE;
}

__global__ void edge_scatter_kernel(const int* __restrict__ ei) {
    int e = blockIdx.x * blockDim.x + threadIdx.x;
    if (e < kE) {
        int d = ei[kE + e];
        int p = atomicAdd(&g_cursor[d], 1);
        g_srcsorted[p] = ei[e];
    }
}

// ---------------- column stats: per-block partials ----------------
__global__ void colstats_part_kernel(const float* __restrict__ in, int rows) {
    int col = threadIdx.x & 127;
    int half = threadIdx.x >> 7;
    float s = 0.f, q = 0.f;
    for (int r = blockIdx.x * 2 + half; r < rows; r += gridDim.x * 2) {
        float v = in[r * kH + col];
        s += v;
        q += v * v;
    }
    __shared__ float ss[256], qq[256];
    ss[threadIdx.x] = s;
    qq[threadIdx.x] = q;
    __syncthreads();
    if (threadIdx.x < 128) {
        g_psum[blockIdx.x * kH + col] = ss[threadIdx.x] + ss[threadIdx.x + 128];
        g_psq[blockIdx.x * kH + col] = qq[threadIdx.x] + qq[threadIdx.x + 128];
    }
}

__global__ void finalize_fold_kernel(int nb, float inv_n, int do_fold,
                                     const float* __restrict__ W, const float* __restrict__ b,
                                     const float* __restrict__ gamma, const float* __restrict__ beta) {
    __shared__ float sm_sg[kH], sm_off[kH];
    int j = threadIdx.x;
    float s = 0.f, q = 0.f;
    for (int bi = 0; bi < nb; bi++) {
        s += g_psum[bi * kH + j];
        q += g_psq[bi * kH + j];
    }
    float m = s * inv_n;
    float v = q * inv_n - m * m;
    float rs = rsqrtf(fmaxf(v, 0.f) + 1e-5f);
    g_mean[j] = m;
    g_rstd[j] = rs;
    if (!do_fold) return;
    float gm = gamma[j], bt = beta[j];
    sm_sg[j] = rs * gm;
    sm_off[j] = bt - m * rs * gm;
    __syncthreads();
    float acc = b[j];
    for (int k = 0; k < kH; k++) {
        float w = W[k * kH + j];
        g_Wt[k * kH + j] = w * sm_sg[k];
        acc += sm_off[k] * w;
    }
    g_bt[j] = acc;
}

__global__ void zero_stats_kernel() {
    int t = threadIdx.x;
    if (t < kH) { g_colsum[t] = 0.f; g_colsq[t] = 0.f; }
}
__global__ void finalize_kernel(float inv_n) {
    int j = threadIdx.x;
    float m = g_colsum[j] * inv_n;
    float v = g_colsq[j] * inv_n - m * m;
    g_mean[j] = m;
    g_rstd[j] = rsqrtf(fmaxf(v, 0.f) + 1e-5f);
}

// ---------------- B-fragment pre-pack (bf16 hi/lo split) ----------------
// uint4[i], i = nt*256 + kk*32 + lane:
//   .x = {hi(W[k0][n]) | hi(W[k0+1][n])<<16}        (b0_hi)
//   .y = {hi(W[k0+8][n]) | hi(W[k0+9][n])<<16}      (b1_hi)
//   .z, .w = lo parts, same positions
// where k0 = kk*16 + tq*2, n = nt*8 + g
__global__ void pack_bfrag_kernel(const float* __restrict__ W, uint4* __restrict__ dst) {
    int i = blockIdx.x * 256 + threadIdx.x;
    if (i >= 4096) return;
    int lane = i & 31;
    int kk = (i >> 5) & 7;
    int nt = i >> 8;
    int g = lane >> 2, tq = lane & 3;
    int n = nt * 8 + g;
    int k0 = kk * 16 + tq * 2;
    float w00 = W[(k0)     * kH + n];
    float w01 = W[(k0 + 1) * kH + n];
    float w10 = W[(k0 + 8) * kH + n];
    float w11 = W[(k0 + 9) * kH + n];
    uint32_t h00 = bfhi(w00), h01 = bfhi(w01), h10 = bfhi(w10), h11 = bfhi(w11);
    uint32_t l00 = bfhi(w00 - bf2f(h00));
    uint32_t l01 = bfhi(w01 - bf2f(h01));
    uint32_t l10 = bfhi(w10 - bf2f(h10));
    uint32_t l11 = bfhi(w11 - bf2f(h11));
    dst[i] = make_uint4(h00 | (h01 << 16), h10 | (h11 << 16),
                        l00 | (l01 << 16), l10 | (l11 << 16));
}

// ---------------- bf16 split mma.sync GEMM v6 ----------------
// out = op_in(A) @ W + bias, via 3-term bf16 split (ahi*bhi + ahi*blo + alo*bhi).
// A staged as hi/lo bf16 tiles; B pre-packed in fragment order.
#define PADH 136   // bf16 elems per A row (272 B); a-frag banks 4g+8kk+tq -> distinct
#define SM_AHI 0
#define SM_ALO 17408
#define SM_B   34816
#define SM_BIA 100352
#define TF_SMEM 100864

#define MMA_BF16(acc, A0, A1, A2, A3, B0, B1) \
    asm volatile("mma.sync.aligned.m16n8k16.row.col.f32.bf16.bf16.f32 " \
        "{%0,%1,%2,%3}, {%4,%5,%6,%7}, {%8,%9}, {%0,%1,%2,%3};" \
        : "+f"((acc)[0]), "+f"((acc)[1]), "+f"((acc)[2]), "+f"((acc)[3]) \
        : "r"(A0), "r"(A1), "r"(A2), "r"(A3), "r"(B0), "r"(B1))

__global__ __launch_bounds__(128, 2) void gemm_bf16_kernel(
    const float* __restrict__ A, const uint4* __restrict__ Bpack,
    const float* __restrict__ bias, float* __restrict__ out,
    int rows, int mode_in, int relu_out,
    const float* __restrict__ gamma, const float* __restrict__ beta) {
    extern __shared__ char smc[];
    char* As_hi = smc + SM_AHI;
    char* As_lo = smc + SM_ALO;
    uint4* Bs4 = (uint4*)(smc + SM_B);
    float* bias_s = (float*)(smc + SM_BIA);

    int t = threadIdx.x;
    int wid = t >> 5, lane = t & 31;
    int row0 = blockIdx.x * 64;

    bias_s[t] = bias[t];

    // stage A tile (64x128) with optional BN+relu, split to bf16 hi/lo
#pragma unroll
    for (int i = 0; i < 16; i++) {
        int idx4 = i * 128 + t;
        int r = idx4 >> 5;
        int c4 = idx4 & 31;
        int grow = row0 + r;
        float4 v = make_float4(0.f, 0.f, 0.f, 0.f);
        if (grow < rows) v = *(const float4*)(A + (size_t)grow * kH + c4 * 4);
        if (mode_in) {
            int k = c4 * 4;
            v.x = fmaxf(fmaf(v.x - g_mean[k + 0], g_rstd[k + 0] * gamma[k + 0], beta[k + 0]), 0.f);
            v.y = fmaxf(fmaf(v.y - g_mean[k + 1], g_rstd[k + 1] * gamma[k + 1], beta[k + 1]), 0.f);
            v.z = fmaxf(fmaf(v.z - g_mean[k + 2], g_rstd[k + 2] * gamma[k + 2], beta[k + 2]), 0.f);
            v.w = fmaxf(fmaf(v.w - g_mean[k + 3], g_rstd[k + 3] * gamma[k + 3], beta[k + 3]), 0.f);
        }
        uint32_t h0 = bfhi(v.x), h1 = bfhi(v.y), h2 = bfhi(v.z), h3 = bfhi(v.w);
        uint32_t l0 = bfhi(v.x - bf2f(h0));
        uint32_t l1 = bfhi(v.y - bf2f(h1));
        uint32_t l2 = bfhi(v.z - bf2f(h2));
        uint32_t l3 = bfhi(v.w - bf2f(h3));
        int off = r * (PADH * 2) + c4 * 8;
        *(uint2*)(As_hi + off) = make_uint2(h0 | (h1 << 16), h2 | (h3 << 16));
        *(uint2*)(As_lo + off) = make_uint2(l0 | (l1 << 16), l2 | (l3 << 16));
    }

    // stage packed B (coalesced)
#pragma unroll
    for (int i = 0; i < 32; i++) Bs4[i * 128 + t] = Bpack[i * 128 + t];
    __syncthreads();

    int g = lane >> 2;
    int tq = lane & 3;
    int wrow = wid * 16;

    float acc[16][4];
#pragma unroll
    for (int nt = 0; nt < 16; nt++)
#pragma unroll
        for (int j = 0; j < 4; j++) acc[nt][j] = 0.f;

    const char* abh = As_hi + (wrow + g) * (PADH * 2) + tq * 4;
    const char* abl = As_lo + (wrow + g) * (PADH * 2) + tq * 4;

#pragma unroll
    for (int kk = 0; kk < 8; kk++) {
        const char* ph = abh + kk * 32;
        const char* pl = abl + kk * 32;
        uint32_t ah0 = *(const uint32_t*)(ph);
        uint32_t ah1 = *(const uint32_t*)(ph + 8 * PADH * 2);
        uint32_t ah2 = *(const uint32_t*)(ph + 16);
        uint32_t ah3 = *(const uint32_t*)(ph + 8 * PADH * 2 + 16);
        uint32_t al0 = *(const uint32_t*)(pl);
        uint32_t al1 = *(const uint32_t*)(pl + 8 * PADH * 2);
        uint32_t al2 = *(const uint32_t*)(pl + 16);
        uint32_t al3 = *(const uint32_t*)(pl + 8 * PADH * 2 + 16);
        const uint4* bk = Bs4 + kk * 32 + lane;
#pragma unroll
        for (int nt = 0; nt < 16; nt++) {
            uint4 b = bk[nt * 256];
            MMA_BF16(acc[nt], ah0, ah1, ah2, ah3, b.x, b.y);   // hi*hi
            MMA_BF16(acc[nt], ah0, ah1, ah2, ah3, b.z, b.w);   // hi*lo
            MMA_BF16(acc[nt], al0, al1, al2, al3, b.x, b.y);   // lo*hi
        }
    }

    int r0 = row0 + wrow + g;
    int r1 = r0 + 8;
#pragma unroll
    for (int nt = 0; nt < 16; nt++) {
        int col = nt * 8 + tq * 2;
        float bx = bias_s[col], by = bias_s[col + 1];
        float o0 = acc[nt][0] + bx, o1 = acc[nt][1] + by;
        float o2 = acc[nt][2] + bx, o3 = acc[nt][3] + by;
        if (relu_out) {
            o0 = fmaxf(o0, 0.f); o1 = fmaxf(o1, 0.f);
            o2 = fmaxf(o2, 0.f); o3 = fmaxf(o3, 0.f);
        }
        if (r0 < rows) *(float2*)(out + (size_t)r0 * kH + col) = make_float2(o0, o1);
        if (r1 < rows) *(float2*)(out + (size_t)r1 * kH + col) = make_float2(o2, o3);
    }
}

// ---------------- scalar GEMM (small, rows<=500) with fused stats ----------------
#define GEMM_SMEM ((128 * 128 + 64 * 128 + 256) * 4)

__global__ __launch_bounds__(256, 2) void gemm_kernel(
    const float* __restrict__ A, const float* __restrict__ W,
    const float* __restrict__ bias, float* __restrict__ out,
    int rows, int mode_in, int relu_out, int do_stats,
    const float* __restrict__ gamma, const float* __restrict__ beta) {
    extern __shared__ float smf[];
    float* Ws = smf;
    float* As = smf + 128 * 128;
    float* colS = As + 64 * 128;
    float* colQ = colS + 128;

    int t = threadIdx.x;
    if (t < 128) { colS[t] = 0.f; colQ[t] = 0.f; }
    int row0 = blockIdx.x * 64;

    const float4* W4 = (const float4*)W;
    float4* Ws4 = (float4*)Ws;
#pragma unroll
    for (int i = 0; i < 16; i++) Ws4[i * 256 + t] = W4[i * 256 + t];

#pragma unroll
    for (int i = 0; i < 8; i++) {
        int idx4 = i * 256 + t;
        int r = idx4 >> 5;
        int c4 = idx4 & 31;
        int grow = row0 + r;
        float4 v = make_float4(0.f, 0.f, 0.f, 0.f);
        if (grow < rows) v = *(const float4*)(A + (size_t)grow * kH + c4 * 4);
        if (mode_in) {
            int k = c4 * 4;
            v.x = fmaxf(fmaf(v.x - g_mean[k + 0], g_rstd[k + 0] * gamma[k + 0], beta[k + 0]), 0.f);
            v.y = fmaxf(fmaf(v.y - g_mean[k + 1], g_rstd[k + 1] * gamma[k + 1], beta[k + 1]), 0.f);
            v.z = fmaxf(fmaf(v.z - g_mean[k + 2], g_rstd[k + 2] * gamma[k + 2], beta[k + 2]), 0.f);
            v.w = fmaxf(fmaf(v.w - g_mean[k + 3], g_rstd[k + 3] * gamma[k + 3], beta[k + 3]), 0.f);
        }
        *(float4*)(As + r * kH + c4 * 4) = v;
    }
    __syncthreads();

    int tc = (t & 31) * 4;
    int tr = (t >> 5) * 8;
    float acc[8][4];
#pragma unroll
    for (int i = 0; i < 8; i++)
#pragma unroll
        for (int j = 0; j < 4; j++) acc[i][j] = 0.f;

#pragma unroll 8
    for (int k = 0; k < kH; k++) {
        float4 w = *(const float4*)(Ws + k * kH + tc);
#pragma unroll
        for (int i = 0; i < 8; i++) {
            float a = As[(tr + i) * kH + k];
            acc[i][0] = fmaf(a, w.x, acc[i][0]);
            acc[i][1] = fmaf(a, w.y, acc[i][1]);
            acc[i][2] = fmaf(a, w.z, acc[i][2]);
            acc[i][3] = fmaf(a, w.w, acc[i][3]);
        }
    }

    float4 b4 = *(const float4*)(bias + tc);
    float sl[4] = {0.f, 0.f, 0.f, 0.f}, ql[4] = {0.f, 0.f, 0.f, 0.f};
#pragma unroll
    for (int i = 0; i < 8; i++) {
        int grow = row0 + tr + i;
        float o0 = acc[i][0] + b4.x;
        float o1 = acc[i][1] + b4.y;
        float o2 = acc[i][2] + b4.z;
        float o3 = acc[i][3] + b4.w;
        if (relu_out) {
            o0 = fmaxf(o0, 0.f); o1 = fmaxf(o1, 0.f);
            o2 = fmaxf(o2, 0.f); o3 = fmaxf(o3, 0.f);
        }
        if (grow < rows) {
            *(float4*)(out + (size_t)grow * kH + tc) = make_float4(o0, o1, o2, o3);
            if (do_stats) {
                sl[0] += o0; ql[0] += o0 * o0;
                sl[1] += o1; ql[1] += o1 * o1;
                sl[2] += o2; ql[2] += o2 * o2;
                sl[3] += o3; ql[3] += o3 * o3;
            }
        }
    }
    if (do_stats) {
        atomicAdd(&colS[tc + 0], sl[0]); atomicAdd(&colQ[tc + 0], ql[0]);
        atomicAdd(&colS[tc + 1], sl[1]); atomicAdd(&colQ[tc + 1], ql[1]);
        atomicAdd(&colS[tc + 2], sl[2]); atomicAdd(&colQ[tc + 2], ql[2]);
        atomicAdd(&colS[tc + 3], sl[3]); atomicAdd(&colQ[tc + 3], ql[3]);
        __syncthreads();
        if (t < 128) {
            atomicAdd(&g_colsum[t], colS[t]);
            atomicAdd(&g_colsq[t], colQ[t]);
        }
    }
}

// ---------------- GIN aggregation (unroll 4) ----------------
__global__ void agg_kernel(const float* __restrict__ h, float* __restrict__ z) {
    int gidx = blockIdx.x * blockDim.x + threadIdx.x;
    int node = gidx >> 5;
    int lane = gidx & 31;
    if (node >= kN) return;
    int beg = g_rowptr[node], end = g_rowptr[node + 1];
    const float4* h4 = (const float4*)h;
    float4 acc = h4[node * 32 + lane];
    float4 acc2 = make_float4(0.f, 0.f, 0.f, 0.f);
    int e = beg;
    for (; e + 4 <= end; e += 4) {
        int s0 = g_srcsorted[e], s1 = g_srcsorted[e + 1];
        int s2 = g_srcsorted[e + 2], s3 = g_srcsorted[e + 3];
        float4 v0 = h4[s0 * 32 + lane];
        float4 v1 = h4[s1 * 32 + lane];
        float4 v2 = h4[s2 * 32 + lane];
        float4 v3 = h4[s3 * 32 + lane];
        acc.x += v0.x + v1.x; acc.y += v0.y + v1.y;
        acc.z += v0.z + v1.z; acc.w += v0.w + v1.w;
        acc2.x += v2.x + v3.x; acc2.y += v2.y + v3.y;
        acc2.z += v2.z + v3.z; acc2.w += v2.w + v3.w;
    }
    for (; e < end; e++) {
        int s = g_srcsorted[e];
        float4 v = h4[s * 32 + lane];
        acc.x += v.x; acc.y += v.y; acc.z += v.z; acc.w += v.w;
    }
    acc.x += acc2.x; acc.y += acc2.y; acc.z += acc2.z; acc.w += acc2.w;
    ((float4*)z)[node * 32 + lane] = acc;
}

// ---------------- pooling: block per graph (batch sorted) ----------------
__global__ void pool_seg_kernel(const float* __restrict__ h, const int* __restrict__ batch) {
    int g = blockIdx.x;
    int t = threadIdx.x;
    int lo = 0, hi = kN;
    while (lo < hi) { int m = (lo + hi) >> 1; if (batch[m] < g) lo = m + 1; else hi = m; }
    int s = lo;
    lo = s; hi = kN;
    while (lo < hi) { int m = (lo + hi) >> 1; if (batch[m] < g + 1) lo = m + 1; else hi = m; }
    int e = lo;
    float acc = 0.f;
    for (int n = s; n < e; n++) acc += h[(size_t)n * kH + t];
    g_pool[g * kH + t] = acc;
}

// ---------------- final head ----------------
__global__ void final_kernel(const float* __restrict__ g2,
                             const float* __restrict__ gamma_h, const float* __restrict__ beta_h,
                             const float* __restrict__ Wcls, const float* __restrict__ bcls,
                             float* __restrict__ out) {
    int row = blockIdx.x;
    int t = threadIdx.x;
    __shared__ float y[kH];
    __shared__ float logits[kC];
    float v = g2[row * kH + t];
    v = fmaf(v - g_mean[t], g_rstd[t] * gamma_h[t], beta_h[t]);
    y[t] = v;
    __syncthreads();
    if (t < kC) {
        float acc = bcls[t];
        for (int k = 0; k < kH; k++) acc = fmaf(y[k], Wcls[k * kC + t], acc);
        logits[t] = acc;
    }
    __syncthreads();
    if (t == 0) {
        float mx = -1e30f;
        for (int c = 0; c < kC; c++) mx = fmaxf(mx, logits[c]);
        float se = 0.f;
        for (int c = 0; c < kC; c++) se += expf(logits[c] - mx);
        float lse = logf(se) + mx;
        for (int c = 0; c < kC; c++) out[row * kC + c] = logits[c] - lse;
    }
}

// ---------------- launcher ----------------
extern "C" void kernel_launch(void* const* d_in, const int* in_sizes, int n_in,
                              void* d_out, int out_size) {
    int iX = 0, iEI = 1, iB = 2, iGF = 3, iBF = 4, iWF = 5, ibF = 6,
        iW1 = 7, ib1 = 8, iGG = 9, iGB = 10, iW2 = 11, ib2 = 12,
        iGFC = 13, iBFC = 14, iWFC = 15, ibFC = 16, iGH = 17, iBH = 18,
        iWC = 19, ibC = 20;
    if (n_in >= 21 && in_sizes[1] != 2 * kE) {
        iGF = 1; iBF = 2; iWF = 3; ibF = 4; iW1 = 5; ib1 = 6; iGG = 7; iGB = 8;
        iW2 = 9; ib2 = 10; iGFC = 11; iBFC = 12; iWFC = 13; ibFC = 14;
        iGH = 15; iBH = 16; iWC = 17; ibC = 18; iEI = 19; iB = 20;
    }
    const float* x          = (const float*)d_in[iX];
    const int*   ei         = (const int*)d_in[iEI];
    const int*   batch      = (const int*)d_in[iB];
    const float* gamma_feat = (const float*)d_in[iGF];
    const float* beta_feat  = (const float*)d_in[iBF];
    const float* W_feat     = (const float*)d_in[iWF];
    const float* b_feat     = (const float*)d_in[ibF];
    const float* gin_W1     = (const float*)d_in[iW1];
    const float* gin_b1     = (const float*)d_in[ib1];
    const float* gin_gamma  = (const float*)d_in[iGG];
    const float* gin_beta   = (const float*)d_in[iGB];
    const float* gin_W2     = (const float*)d_in[iW2];
    const float* gin_b2     = (const float*)d_in[ib2];
    const float* gamma_fc   = (const float*)d_in[iGFC];
    const float* beta_fc    = (const float*)d_in[iBFC];
    const float* W_fc       = (const float*)d_in[iWFC];
    const float* b_fc       = (const float*)d_in[ibFC];
    const float* gamma_h    = (const float*)d_in[iGH];
    const float* beta_h     = (const float*)d_in[iBH];
    const float* W_cls      = (const float*)d_in[iWC];
    const float* b_cls      = (const float*)d_in[ibC];
    float* out = (float*)d_out;

    cudaFuncSetAttribute(gemm_kernel, cudaFuncAttributeMaxDynamicSharedMemorySize, GEMM_SMEM);
    cudaFuncSetAttribute(gemm_bf16_kernel, cudaFuncAttributeMaxDynamicSharedMemorySize, TF_SMEM);

    float *bufA, *bufB, *bufC, *pool, *pool2, *Wt, *bt;
    uint4* Bpack;
    cudaGetSymbolAddress((void**)&bufA, g_bufA);
    cudaGetSymbolAddress((void**)&bufB, g_bufB);
    cudaGetSymbolAddress((void**)&bufC, g_bufC);
    cudaGetSymbolAddress((void**)&pool, g_pool);
    cudaGetSymbolAddress((void**)&pool2, g_pool2);
    cudaGetSymbolAddress((void**)&Wt, g_Wt);
    cudaGetSymbolAddress((void**)&bt, g_bt);
    cudaGetSymbolAddress((void**)&Bpack, g_Bpack);

    const int TB = 256;
    const int gridN = (kN + TB - 1) / TB;
    const int gridE = (kE + TB - 1) / TB;
    const int gridWarpN = (kN * 32 + TB - 1) / TB;
    const int gridTF = (kN + 63) / 64;
    const int gridGemmG = (kG + 63) / 64;

    // feat GEMM at profiled launch index 3.
    colstats_part_kernel<<<NSTAT, TB>>>(x, kN);                               // 0
    finalize_fold_kernel<<<1, 128>>>(NSTAT, 1.0f / kN, 1,
                                     W_feat, b_feat, gamma_feat, beta_feat);  // 1
    pack_bfrag_kernel<<<16, 256>>>(Wt, Bpack);                                // 2
    gemm_bf16_kernel<<<gridTF, 128, TF_SMEM>>>(x, Bpack, bt, bufA,
                                               kN, 0, 1, nullptr, nullptr);   // 3 <- profiled

    // CSR by dst (before first agg)
    zero_cnt_kernel<<<gridN, TB>>>();
    edge_count_kernel<<<gridE, TB>>>(ei);
    scan_kernel<<<1, 1024>>>();
    edge_scatter_kernel<<<gridE, TB>>>(ei);

    // pre-pack GIN weights
    for (int i = 0; i < NUM_GIN; i++) {
        pack_bfrag_kernel<<<16, 256>>>(gin_W1 + i * kH * kH, Bpack + (1 + i) * 4096);
        pack_bfrag_kernel<<<16, 256>>>(gin_W2 + i * kH * kH, Bpack + (4 + i) * 4096);
    }

    // GIN layers
    for (int i = 0; i < NUM_GIN; i++) {
        agg_kernel<<<gridWarpN, TB>>>(bufA, bufB);
        gemm_bf16_kernel<<<gridTF, 128, TF_SMEM>>>(bufB, Bpack + (1 + i) * 4096,
                                                   gin_b1 + i * kH, bufC, kN, 0, 0,
                                                   nullptr, nullptr);
        colstats_part_kernel<<<NSTAT, TB>>>(bufC, kN);
        finalize_fold_kernel<<<1, 128>>>(NSTAT, 1.0f / kN, 0,
                                         nullptr, nullptr, nullptr, nullptr);
        gemm_bf16_kernel<<<gridTF, 128, TF_SMEM>>>(bufC, Bpack + (4 + i) * 4096,
                                                   gin_b2 + i * kH, bufA, kN, 1, 1,
                                                   gin_gamma + i * kH, gin_beta + i * kH);
    }

    // pool (segment sum, batch sorted)
    pool_seg_kernel<<<kG, 128>>>(bufA, batch);

    // g2 = relu(BN(g) @ W_fc + b_fc) (BN folded); stats of g2 for bn_h
    colstats_part_kernel<<<4, TB>>>(pool, kG);
    finalize_fold_kernel<<<1, 128>>>(4, 1.0f / kG, 1, W_fc, b_fc, gamma_fc, beta_fc);
    zero_stats_kernel<<<1, 128>>>();
    gemm_kernel<<<gridGemmG, TB, GEMM_SMEM>>>(pool, Wt, bt, pool2, kG, 0, 1, 1, nullptr, nullptr);
    finalize_kernel<<<1, 128>>>(1.0f / kG);

    // classifier + log_softmax
    final_kernel<<<kG, 128>>>(pool2, gamma_h, beta_h, W_cls, b_cls, out);
}

// round 11
// speedup vs baseline: 1.1825x; 1.1324x over previous
#include <cuda_runtime.h>
#include <math.h>
#include <stdint.h>

#define kN 50000
#define kE 600000
#define kH 128
#define kG 500
#define kC 10
#define NUM_GIN 3
#define NSTAT 256   // partial-stat blocks for big tensors

// ---------------- device scratch (static; no allocation) ----------------
__device__ __align__(16) float g_bufA[kN * kH];
__device__ __align__(16) float g_bufB[kN * kH];
__device__ __align__(16) float g_bufC[kN * kH];
__device__ int   g_cnt[kN];
__device__ int   g_rowptr[kN + 1];
__device__ int   g_cursor[kN];
__device__ int   g_srcsorted[kE];
__device__ __align__(16) float g_psum[NSTAT * kH];
__device__ __align__(16) float g_psq[NSTAT * kH];
__device__ __align__(16) float g_colsum[kH];
__device__ __align__(16) float g_colsq[kH];
__device__ __align__(16) float g_mean[kH];
__device__ __align__(16) float g_rstd[kH];
__device__ __align__(16) float g_Wt[kH * kH];
__device__ __align__(16) float g_bt[kH];
__device__ __align__(16) float g_Bpack[7][16384];  // packed tf32 B fragments (64 KB each)
__device__ __align__(16) float g_pool[kG * kH];
__device__ __align__(16) float g_pool2[kG * kH];

__device__ __forceinline__ uint32_t f2tf32(float f) {
    uint32_t r;
    asm("cvt.rna.tf32.f32 %0, %1;" : "=r"(r) : "f"(f));
    return r;
}

// ---------------- CSR build ----------------
__global__ void zero_cnt_kernel() {
    int i = blockIdx.x * blockDim.x + threadIdx.x;
    if (i < kN) g_cnt[i] = 0;
}

__global__ void edge_count_kernel(const int* __restrict__ ei) {
    int e = blockIdx.x * blockDim.x + threadIdx.x;
    if (e < kE) atomicAdd(&g_cnt[ei[kE + e]], 1);
}

__global__ void scan_kernel() {
    __shared__ int s[1024];
    int t = threadIdx.x;
    const int CH = (kN + 1023) / 1024;
    int base = t * CH;
    int sum = 0;
    for (int i = 0; i < CH; i++) {
        int idx = base + i;
        if (idx < kN) sum += g_cnt[idx];
    }
    s[t] = sum;
    __syncthreads();
    for (int off = 1; off < 1024; off <<= 1) {
        int v = (t >= off) ? s[t - off] : 0;
        __syncthreads();
        s[t] += v;
        __syncthreads();
    }
    int run = (t == 0) ? 0 : s[t - 1];
    for (int i = 0; i < CH; i++) {
        int idx = base + i;
        if (idx < kN) {
            g_rowptr[idx] = run;
            g_cursor[idx] = run;
            run += g_cnt[idx];
        }
    }
    if (t == 1023) g_rowptr[kN] = kE;
}

__global__ void edge_scatter_kernel(const int* __restrict__ ei) {
    int e = blockIdx.x * blockDim.x + threadIdx.x;
    if (e < kE) {
        int d = ei[kE + e];
        int p = atomicAdd(&g_cursor[d], 1);
        g_srcsorted[p] = ei[e];
    }
}

// ---------------- column stats: per-block partials ----------------
__global__ void colstats_part_kernel(const float* __restrict__ in, int rows) {
    int col = threadIdx.x & 127;
    int half = threadIdx.x >> 7;
    float s = 0.f, q = 0.f;
    for (int r = blockIdx.x * 2 + half; r < rows; r += gridDim.x * 2) {
        float v = in[r * kH + col];
        s += v;
        q += v * v;
    }
    __shared__ float ss[256], qq[256];
    ss[threadIdx.x] = s;
    qq[threadIdx.x] = q;
    __syncthreads();
    if (threadIdx.x < 128) {
        g_psum[blockIdx.x * kH + col] = ss[threadIdx.x] + ss[threadIdx.x + 128];
        g_psq[blockIdx.x * kH + col] = qq[threadIdx.x] + qq[threadIdx.x + 128];
    }
}

__global__ void finalize_fold_kernel(int nb, float inv_n, int do_fold,
                                     const float* __restrict__ W, const float* __restrict__ b,
                                     const float* __restrict__ gamma, const float* __restrict__ beta) {
    __shared__ float sm_sg[kH], sm_off[kH];
    int j = threadIdx.x;
    float s = 0.f, q = 0.f;
    for (int bi = 0; bi < nb; bi++) {
        s += g_psum[bi * kH + j];
        q += g_psq[bi * kH + j];
    }
    float m = s * inv_n;
    float v = q * inv_n - m * m;
    float rs = rsqrtf(fmaxf(v, 0.f) + 1e-5f);
    g_mean[j] = m;
    g_rstd[j] = rs;
    if (!do_fold) return;
    float gm = gamma[j], bt = beta[j];
    sm_sg[j] = rs * gm;
    sm_off[j] = bt - m * rs * gm;
    __syncthreads();
    float acc = b[j];
    for (int k = 0; k < kH; k++) {
        float w = W[k * kH + j];
        g_Wt[k * kH + j] = w * sm_sg[k];
        acc += sm_off[k] * w;
    }
    g_bt[j] = acc;
}

__global__ void zero_stats_kernel() {
    int t = threadIdx.x;
    if (t < kH) { g_colsum[t] = 0.f; g_colsq[t] = 0.f; }
}
__global__ void finalize_kernel(float inv_n) {
    int j = threadIdx.x;
    float m = g_colsum[j] * inv_n;
    float v = g_colsq[j] * inv_n - m * m;
    g_mean[j] = m;
    g_rstd[j] = rsqrtf(fmaxf(v, 0.f) + 1e-5f);
}

// ---------------- B-fragment pre-pack (tf32, nt-major layout) ----------------
__global__ void pack_bfrag_kernel(const float* __restrict__ W, float* __restrict__ dst) {
    int i = blockIdx.x * 256 + threadIdx.x;
    if (i >= 4096) return;
    int lane = i & 31;
    int kk2 = (i >> 5) & 7;
    int nt = i >> 8;
    int g = lane >> 2, tq = lane & 3;
    int n = nt * 8 + g;
    int k0 = kk2 * 16 + tq;
    float4 v;
    v.x = __uint_as_float(f2tf32(W[(k0)      * kH + n]));
    v.y = __uint_as_float(f2tf32(W[(k0 + 4)  * kH + n]));
    v.z = __uint_as_float(f2tf32(W[(k0 + 8)  * kH + n]));
    v.w = __uint_as_float(f2tf32(W[(k0 + 12) * kH + n]));
    ((float4*)dst)[i] = v;
}

// ---------------- tf32 mma.sync GEMM v7: 64x64 N-split tiles, 3 CTAs/SM ----------------
#define PAD 132   // A-frag LDS bank = 4g+tq -> conflict-free
#define TF_SMEM ((64 * PAD + 8192 + 128) * 4)   // A 33792B + Bhalf 32768B + bias 512B

__global__ __launch_bounds__(128, 3) void gemm_tf32_kernel(
    const float* __restrict__ A, const float* __restrict__ Bpack,
    const float* __restrict__ bias, float* __restrict__ out,
    int rows, int mode_in, int relu_out,
    const float* __restrict__ gamma, const float* __restrict__ beta) {
    extern __shared__ float sm[];
    float* As = sm;                    // [64][PAD]
    float* Bs = sm + 64 * PAD;         // 8192 floats = half pack (cols 64*by..)
    float* bias_s = Bs + 8192;         // [128]

    int t = threadIdx.x;
    int wid = t >> 5, lane = t & 31;
    int row0 = blockIdx.x * 64;
    int nby = blockIdx.y;              // 0 or 1: which 64-column half

    bias_s[t] = bias[t];

    // stage A tile (64x128) with optional BN+relu, tf32-rounded
#pragma unroll
    for (int i = 0; i < 16; i++) {
        int idx4 = i * 128 + t;
        int r = idx4 >> 5;
        int c4 = idx4 & 31;
        int grow = row0 + r;
        float4 v = make_float4(0.f, 0.f, 0.f, 0.f);
        if (grow < rows) v = *(const float4*)(A + (size_t)grow * kH + c4 * 4);
        if (mode_in) {
            int k = c4 * 4;
            v.x = fmaxf(fmaf(v.x - g_mean[k + 0], g_rstd[k + 0] * gamma[k + 0], beta[k + 0]), 0.f);
            v.y = fmaxf(fmaf(v.y - g_mean[k + 1], g_rstd[k + 1] * gamma[k + 1], beta[k + 1]), 0.f);
            v.z = fmaxf(fmaf(v.z - g_mean[k + 2], g_rstd[k + 2] * gamma[k + 2], beta[k + 2]), 0.f);
            v.w = fmaxf(fmaf(v.w - g_mean[k + 3], g_rstd[k + 3] * gamma[k + 3], beta[k + 3]), 0.f);
        }
        float* dst = As + r * PAD + c4 * 4;
        dst[0] = __uint_as_float(f2tf32(v.x));
        dst[1] = __uint_as_float(f2tf32(v.y));
        dst[2] = __uint_as_float(f2tf32(v.z));
        dst[3] = __uint_as_float(f2tf32(v.w));
    }

    // stage packed B half (nt-major pack -> contiguous 2048 float4)
    {
        const float4* Bp4 = ((const float4*)Bpack) + nby * 2048;
        float4* Bs4 = (float4*)Bs;
#pragma unroll
        for (int i = 0; i < 16; i++) Bs4[i * 128 + t] = Bp4[i * 128 + t];
    }
    __syncthreads();

    int g = lane >> 2;
    int tq = lane & 3;
    int wrow = wid * 16;

    float acc[8][4];
#pragma unroll
    for (int nt = 0; nt < 8; nt++)
#pragma unroll
        for (int j = 0; j < 4; j++) acc[nt][j] = 0.f;

    const float* abase = As + (wrow + g) * PAD + tq;
    const float4* bp = ((const float4*)Bs) + lane;

#pragma unroll
    for (int kk2 = 0; kk2 < 8; kk2++) {
        const float* ap = abase + kk2 * 16;
        uint32_t a0[4], a1[4];
        a0[0] = __float_as_uint(ap[0]);
        a0[1] = __float_as_uint(ap[8 * PAD]);
        a0[2] = __float_as_uint(ap[4]);
        a0[3] = __float_as_uint(ap[8 * PAD + 4]);
        a1[0] = __float_as_uint(ap[8]);
        a1[1] = __float_as_uint(ap[8 * PAD + 8]);
        a1[2] = __float_as_uint(ap[12]);
        a1[3] = __float_as_uint(ap[8 * PAD + 12]);
        const float4* bk = bp + kk2 * 32;
#pragma unroll
        for (int nt = 0; nt < 8; nt++) {
            float4 b = bk[nt * 256];
            asm volatile(
                "mma.sync.aligned.m16n8k8.row.col.f32.tf32.tf32.f32 "
                "{%0,%1,%2,%3}, {%4,%5,%6,%7}, {%8,%9}, {%0,%1,%2,%3};"
                : "+f"(acc[nt][0]), "+f"(acc[nt][1]), "+f"(acc[nt][2]), "+f"(acc[nt][3])
                : "r"(a0[0]), "r"(a0[1]), "r"(a0[2]), "r"(a0[3]),
                  "r"(__float_as_uint(b.x)), "r"(__float_as_uint(b.y)));
            asm volatile(
                "mma.sync.aligned.m16n8k8.row.col.f32.tf32.tf32.f32 "
                "{%0,%1,%2,%3}, {%4,%5,%6,%7}, {%8,%9}, {%0,%1,%2,%3};"
                : "+f"(acc[nt][0]), "+f"(acc[nt][1]), "+f"(acc[nt][2]), "+f"(acc[nt][3])
                : "r"(a1[0]), "r"(a1[1]), "r"(a1[2]), "r"(a1[3]),
                  "r"(__float_as_uint(b.z)), "r"(__float_as_uint(b.w)));
        }
    }

    int r0 = row0 + wrow + g;
    int r1 = r0 + 8;
#pragma unroll
    for (int nt = 0; nt < 8; nt++) {
        int col = nby * 64 + nt * 8 + tq * 2;
        float bx = bias_s[col], by = bias_s[col + 1];
        float o0 = acc[nt][0] + bx, o1 = acc[nt][1] + by;
        float o2 = acc[nt][2] + bx, o3 = acc[nt][3] + by;
        if (relu_out) {
            o0 = fmaxf(o0, 0.f); o1 = fmaxf(o1, 0.f);
            o2 = fmaxf(o2, 0.f); o3 = fmaxf(o3, 0.f);
        }
        if (r0 < rows) *(float2*)(out + (size_t)r0 * kH + col) = make_float2(o0, o1);
        if (r1 < rows) *(float2*)(out + (size_t)r1 * kH + col) = make_float2(o2, o3);
    }
}

// ---------------- scalar GEMM (small, rows<=500) with fused stats ----------------
#define GEMM_SMEM ((128 * 128 + 64 * 128 + 256) * 4)

__global__ __launch_bounds__(256, 2) void gemm_kernel(
    const float* __restrict__ A, const float* __restrict__ W,
    const float* __restrict__ bias, float* __restrict__ out,
    int rows, int mode_in, int relu_out, int do_stats,
    const float* __restrict__ gamma, const float* __restrict__ beta) {
    extern __shared__ float smf[];
    float* Ws = smf;
    float* As = smf + 128 * 128;
    float* colS = As + 64 * 128;
    float* colQ = colS + 128;

    int t = threadIdx.x;
    if (t < 128) { colS[t] = 0.f; colQ[t] = 0.f; }
    int row0 = blockIdx.x * 64;

    const float4* W4 = (const float4*)W;
    float4* Ws4 = (float4*)Ws;
#pragma unroll
    for (int i = 0; i < 16; i++) Ws4[i * 256 + t] = W4[i * 256 + t];

#pragma unroll
    for (int i = 0; i < 8; i++) {
        int idx4 = i * 256 + t;
        int r = idx4 >> 5;
        int c4 = idx4 & 31;
        int grow = row0 + r;
        float4 v = make_float4(0.f, 0.f, 0.f, 0.f);
        if (grow < rows) v = *(const float4*)(A + (size_t)grow * kH + c4 * 4);
        if (mode_in) {
            int k = c4 * 4;
            v.x = fmaxf(fmaf(v.x - g_mean[k + 0], g_rstd[k + 0] * gamma[k + 0], beta[k + 0]), 0.f);
            v.y = fmaxf(fmaf(v.y - g_mean[k + 1], g_rstd[k + 1] * gamma[k + 1], beta[k + 1]), 0.f);
            v.z = fmaxf(fmaf(v.z - g_mean[k + 2], g_rstd[k + 2] * gamma[k + 2], beta[k + 2]), 0.f);
            v.w = fmaxf(fmaf(v.w - g_mean[k + 3], g_rstd[k + 3] * gamma[k + 3], beta[k + 3]), 0.f);
        }
        *(float4*)(As + r * kH + c4 * 4) = v;
    }
    __syncthreads();

    int tc = (t & 31) * 4;
    int tr = (t >> 5) * 8;
    float acc[8][4];
#pragma unroll
    for (int i = 0; i < 8; i++)
#pragma unroll
        for (int j = 0; j < 4; j++) acc[i][j] = 0.f;

#pragma unroll 8
    for (int k = 0; k < kH; k++) {
        float4 w = *(const float4*)(Ws + k * kH + tc);
#pragma unroll
        for (int i = 0; i < 8; i++) {
            float a = As[(tr + i) * kH + k];
            acc[i][0] = fmaf(a, w.x, acc[i][0]);
            acc[i][1] = fmaf(a, w.y, acc[i][1]);
            acc[i][2] = fmaf(a, w.z, acc[i][2]);
            acc[i][3] = fmaf(a, w.w, acc[i][3]);
        }
    }

    float4 b4 = *(const float4*)(bias + tc);
    float sl[4] = {0.f, 0.f, 0.f, 0.f}, ql[4] = {0.f, 0.f, 0.f, 0.f};
#pragma unroll
    for (int i = 0; i < 8; i++) {
        int grow = row0 + tr + i;
        float o0 = acc[i][0] + b4.x;
        float o1 = acc[i][1] + b4.y;
        float o2 = acc[i][2] + b4.z;
        float o3 = acc[i][3] + b4.w;
        if (relu_out) {
            o0 = fmaxf(o0, 0.f); o1 = fmaxf(o1, 0.f);
            o2 = fmaxf(o2, 0.f); o3 = fmaxf(o3, 0.f);
        }
        if (grow < rows) {
            *(float4*)(out + (size_t)grow * kH + tc) = make_float4(o0, o1, o2, o3);
            if (do_stats) {
                sl[0] += o0; ql[0] += o0 * o0;
                sl[1] += o1; ql[1] += o1 * o1;
                sl[2] += o2; ql[2] += o2 * o2;
                sl[3] += o3; ql[3] += o3 * o3;
            }
        }
    }
    if (do_stats) {
        atomicAdd(&colS[tc + 0], sl[0]); atomicAdd(&colQ[tc + 0], ql[0]);
        atomicAdd(&colS[tc + 1], sl[1]); atomicAdd(&colQ[tc + 1], ql[1]);
        atomicAdd(&colS[tc + 2], sl[2]); atomicAdd(&colQ[tc + 2], ql[2]);
        atomicAdd(&colS[tc + 3], sl[3]); atomicAdd(&colQ[tc + 3], ql[3]);
        __syncthreads();
        if (t < 128) {
            atomicAdd(&g_colsum[t], colS[t]);
            atomicAdd(&g_colsq[t], colQ[t]);
        }
    }
}

// ---------------- GIN aggregation (unroll 4) ----------------
__global__ void agg_kernel(const float* __restrict__ h, float* __restrict__ z) {
    int gidx = blockIdx.x * blockDim.x + threadIdx.x;
    int node = gidx >> 5;
    int lane = gidx & 31;
    if (node >= kN) return;
    int beg = g_rowptr[node], end = g_rowptr[node + 1];
    const float4* h4 = (const float4*)h;
    float4 acc = h4[node * 32 + lane];
    float4 acc2 = make_float4(0.f, 0.f, 0.f, 0.f);
    int e = beg;
    for (; e + 4 <= end; e += 4) {
        int s0 = g_srcsorted[e], s1 = g_srcsorted[e + 1];
        int s2 = g_srcsorted[e + 2], s3 = g_srcsorted[e + 3];
        float4 v0 = h4[s0 * 32 + lane];
        float4 v1 = h4[s1 * 32 + lane];
        float4 v2 = h4[s2 * 32 + lane];
        float4 v3 = h4[s3 * 32 + lane];
        acc.x += v0.x + v1.x; acc.y += v0.y + v1.y;
        acc.z += v0.z + v1.z; acc.w += v0.w + v1.w;
        acc2.x += v2.x + v3.x; acc2.y += v2.y + v3.y;
        acc2.z += v2.z + v3.z; acc2.w += v2.w + v3.w;
    }
    for (; e < end; e++) {
        int s = g_srcsorted[e];
        float4 v = h4[s * 32 + lane];
        acc.x += v.x; acc.y += v.y; acc.z += v.z; acc.w += v.w;
    }
    acc.x += acc2.x; acc.y += acc2.y; acc.z += acc2.z; acc.w += acc2.w;
    ((float4*)z)[node * 32 + lane] = acc;
}

// ---------------- pooling: block per graph (batch sorted) ----------------
__global__ void pool_seg_kernel(const float* __restrict__ h, const int* __restrict__ batch) {
    int g = blockIdx.x;
    int t = threadIdx.x;
    int lo = 0, hi = kN;
    while (lo < hi) { int m = (lo + hi) >> 1; if (batch[m] < g) lo = m + 1; else hi = m; }
    int s = lo;
    lo = s; hi = kN;
    while (lo < hi) { int m = (lo + hi) >> 1; if (batch[m] < g + 1) lo = m + 1; else hi = m; }
    int e = lo;
    float acc = 0.f;
    for (int n = s; n < e; n++) acc += h[(size_t)n * kH + t];
    g_pool[g * kH + t] = acc;
}

// ---------------- final head ----------------
__global__ void final_kernel(const float* __restrict__ g2,
                             const float* __restrict__ gamma_h, const float* __restrict__ beta_h,
                             const float* __restrict__ Wcls, const float* __restrict__ bcls,
                             float* __restrict__ out) {
    int row = blockIdx.x;
    int t = threadIdx.x;
    __shared__ float y[kH];
    __shared__ float logits[kC];
    float v = g2[row * kH + t];
    v = fmaf(v - g_mean[t], g_rstd[t] * gamma_h[t], beta_h[t]);
    y[t] = v;
    __syncthreads();
    if (t < kC) {
        float acc = bcls[t];
        for (int k = 0; k < kH; k++) acc = fmaf(y[k], Wcls[k * kC + t], acc);
        logits[t] = acc;
    }
    __syncthreads();
    if (t == 0) {
        float mx = -1e30f;
        for (int c = 0; c < kC; c++) mx = fmaxf(mx, logits[c]);
        float se = 0.f;
        for (int c = 0; c < kC; c++) se += expf(logits[c] - mx);
        float lse = logf(se) + mx;
        for (int c = 0; c < kC; c++) out[row * kC + c] = logits[c] - lse;
    }
}

// ---------------- launcher ----------------
extern "C" void kernel_launch(void* const* d_in, const int* in_sizes, int n_in,
                              void* d_out, int out_size) {
    int iX = 0, iEI = 1, iB = 2, iGF = 3, iBF = 4, iWF = 5, ibF = 6,
        iW1 = 7, ib1 = 8, iGG = 9, iGB = 10, iW2 = 11, ib2 = 12,
        iGFC = 13, iBFC = 14, iWFC = 15, ibFC = 16, iGH = 17, iBH = 18,
        iWC = 19, ibC = 20;
    if (n_in >= 21 && in_sizes[1] != 2 * kE) {
        iGF = 1; iBF = 2; iWF = 3; ibF = 4; iW1 = 5; ib1 = 6; iGG = 7; iGB = 8;
        iW2 = 9; ib2 = 10; iGFC = 11; iBFC = 12; iWFC = 13; ibFC = 14;
        iGH = 15; iBH = 16; iWC = 17; ibC = 18; iEI = 19; iB = 20;
    }
    const float* x          = (const float*)d_in[iX];
    const int*   ei         = (const int*)d_in[iEI];
    const int*   batch      = (const int*)d_in[iB];
    const float* gamma_feat = (const float*)d_in[iGF];
    const float* beta_feat  = (const float*)d_in[iBF];
    const float* W_feat     = (const float*)d_in[iWF];
    const float* b_feat     = (const float*)d_in[ibF];
    const float* gin_W1     = (const float*)d_in[iW1];
    const float* gin_b1     = (const float*)d_in[ib1];
    const float* gin_gamma  = (const float*)d_in[iGG];
    const float* gin_beta   = (const float*)d_in[iGB];
    const float* gin_W2     = (const float*)d_in[iW2];
    const float* gin_b2     = (const float*)d_in[ib2];
    const float* gamma_fc   = (const float*)d_in[iGFC];
    const float* beta_fc    = (const float*)d_in[iBFC];
    const float* W_fc       = (const float*)d_in[iWFC];
    const float* b_fc       = (const float*)d_in[ibFC];
    const float* gamma_h    = (const float*)d_in[iGH];
    const float* beta_h     = (const float*)d_in[iBH];
    const float* W_cls      = (const float*)d_in[iWC];
    const float* b_cls      = (const float*)d_in[ibC];
    float* out = (float*)d_out;

    cudaFuncSetAttribute(gemm_kernel, cudaFuncAttributeMaxDynamicSharedMemorySize, GEMM_SMEM);
    cudaFuncSetAttribute(gemm_tf32_kernel, cudaFuncAttributeMaxDynamicSharedMemorySize, TF_SMEM);

    float *bufA, *bufB, *bufC, *pool, *pool2, *Wt, *bt, *Bpack;
    cudaGetSymbolAddress((void**)&bufA, g_bufA);
    cudaGetSymbolAddress((void**)&bufB, g_bufB);
    cudaGetSymbolAddress((void**)&bufC, g_bufC);
    cudaGetSymbolAddress((void**)&pool, g_pool);
    cudaGetSymbolAddress((void**)&pool2, g_pool2);
    cudaGetSymbolAddress((void**)&Wt, g_Wt);
    cudaGetSymbolAddress((void**)&bt, g_bt);
    cudaGetSymbolAddress((void**)&Bpack, g_Bpack);

    // side stream + fork/join events; created lazily on the (pre-capture)
    // correctness call, reused identically on every call thereafter.
    static cudaStream_t s2 = nullptr;
    static cudaEvent_t evFork = nullptr, evJoin = nullptr;
    if (s2 == nullptr) {
        cudaStreamCreateWithFlags(&s2, cudaStreamNonBlocking);
        cudaEventCreateWithFlags(&evFork, cudaEventDisableTiming);
        cudaEventCreateWithFlags(&evJoin, cudaEventDisableTiming);
    }

    const int TB = 256;
    const int gridN = (kN + TB - 1) / TB;
    const int gridE = (kE + TB - 1) / TB;
    const int gridWarpN = (kN * 32 + TB - 1) / TB;
    const dim3 gridTF((kN + 63) / 64, 2);
    const int gridGemmG = (kG + 63) / 64;

    // fork side stream off the capture/main stream (depends on nothing yet)
    cudaEventRecord(evFork, 0);
    cudaStreamWaitEvent(s2, evFork, 0);

    // main chain head; feat GEMM at kernel launch index 3 (profiled slot)
    colstats_part_kernel<<<NSTAT, TB>>>(x, kN);                               // 0
    finalize_fold_kernel<<<1, 128>>>(NSTAT, 1.0f / kN, 1,
                                     W_feat, b_feat, gamma_feat, beta_feat);  // 1
    pack_bfrag_kernel<<<16, 256>>>(Wt, Bpack);                                // 2
    gemm_tf32_kernel<<<gridTF, 128, TF_SMEM>>>(x, Bpack, bt, bufA,
                                               kN, 0, 1, nullptr, nullptr);   // 3 <- profiled

    // side stream: CSR build + GIN weight packs (overlap the head chain)
    zero_cnt_kernel<<<gridN, TB, 0, s2>>>();
    edge_count_kernel<<<gridE, TB, 0, s2>>>(ei);
    scan_kernel<<<1, 1024, 0, s2>>>();
    edge_scatter_kernel<<<gridE, TB, 0, s2>>>(ei);
    for (int i = 0; i < NUM_GIN; i++) {
        pack_bfrag_kernel<<<16, 256, 0, s2>>>(gin_W1 + i * kH * kH, Bpack + (1 + i) * 16384);
        pack_bfrag_kernel<<<16, 256, 0, s2>>>(gin_W2 + i * kH * kH, Bpack + (4 + i) * 16384);
    }
    cudaEventRecord(evJoin, s2);

    // join before the first aggregation (needs CSR + packs)
    cudaStreamWaitEvent(0, evJoin, 0);

    // GIN layers
    for (int i = 0; i < NUM_GIN; i++) {
        agg_kernel<<<gridWarpN, TB>>>(bufA, bufB);
        gemm_tf32_kernel<<<gridTF, 128, TF_SMEM>>>(bufB, Bpack + (1 + i) * 16384,
                                                   gin_b1 + i * kH, bufC, kN, 0, 0,
                                                   nullptr, nullptr);
        colstats_part_kernel<<<NSTAT, TB>>>(bufC, kN);
        finalize_fold_kernel<<<1, 128>>>(NSTAT, 1.0f / kN, 0,
                                         nullptr, nullptr, nullptr, nullptr);
        gemm_tf32_kernel<<<gridTF, 128, TF_SMEM>>>(bufC, Bpack + (4 + i) * 16384,
                                                   gin_b2 + i * kH, bufA, kN, 1, 1,
                                                   gin_gamma + i * kH, gin_beta + i * kH);
    }

    // pool (segment sum, batch sorted)
    pool_seg_kernel<<<kG, 128>>>(bufA, batch);

    // g2 = relu(BN(g) @ W_fc + b_fc) (BN folded); stats of g2 for bn_h
    colstats_part_kernel<<<4, TB>>>(pool, kG);
    finalize_fold_kernel<<<1, 128>>>(4, 1.0f / kG, 1, W_fc, b_fc, gamma_fc, beta_fc);
    zero_stats_kernel<<<1, 128>>>();
    gemm_kernel<<<gridGemmG, TB, GEMM_SMEM>>>(pool, Wt, bt, pool2, kG, 0, 1, 1, nullptr, nullptr);
    finalize_kernel<<<1, 128>>>(1.0f / kG);

    // classifier + log_softmax
    final_kernel<<<kG, 128>>>(pool2, gamma_h, beta_h, W_cls, b_cls, out);
}